// round 12
// baseline (speedup 1.0000x reference)
#include <cuda_runtime.h>
#include <cstdint>

using u64 = unsigned long long;

// Problem constants
constexpr int B_ = 16, C_ = 128, H_ = 72, W_ = 200, K_ = 9;
constexpr int CS = H_ * W_;
constexpr size_t BS = (size_t)C_ * CS;
constexpr size_t TOTAL = (size_t)B_ * BS;
constexpr int NCIP = C_ / 2;             // 64 ci-pairs
constexpr int NR = NCIP * K_;            // 576 weight rows (r = cip*9+k)
constexpr int TCO = 16;                  // c_out per CTA
constexpr int NCTA = C_ / TCO;           // 8 CTAs per cluster (one image)

// Scratch: transposed layout + re-laid-out weights (4 directions)
// g_wp2[dir][r][co]: u64 = pack2(w[co][2cip][k], w[co][2cip+1][k]), co 0..127
__device__ float g_tbuf[TOTAL];
__device__ __align__(16) u64 g_wp2[4 * NR * C_];

__device__ __forceinline__ void fma2(u64& d, u64 a, u64 b) {
    asm("fma.rn.f32x2 %0, %1, %2, %0;" : "+l"(d) : "l"(a), "l"(b));
}
__device__ __forceinline__ u64 pack2(float a, float b) {
    u64 r; asm("mov.b64 %0, {%1, %2};" : "=l"(r) : "f"(a), "f"(b)); return r;
}
__device__ __forceinline__ float hsum2(u64 v) {
    float x, y; asm("mov.b64 {%0, %1}, %2;" : "=f"(x), "=f"(y) : "l"(v));
    return x + y;
}
__device__ __forceinline__ void cp_async16(uint32_t saddr, const void* g) {
    asm volatile("cp.async.cg.shared.global [%0], [%1], 16;" :: "r"(saddr), "l"(g));
}
__device__ __forceinline__ void cp_async_wait_all() {
    asm volatile("cp.async.commit_group;\n\tcp.async.wait_group 0;" ::: "memory");
}
__device__ __forceinline__ void cluster_barrier() {
    asm volatile("barrier.cluster.arrive.aligned;" ::: "memory");
    asm volatile("barrier.cluster.wait.aligned;" ::: "memory");
}

__global__ void prep_weights(const float* w0, const float* w1,
                             const float* w2, const float* w3) {
    const float* ws[4] = {w0, w1, w2, w3};
    const int tot = NR * C_;
    for (int i = blockIdx.x * blockDim.x + threadIdx.x; i < 4 * tot;
         i += gridDim.x * blockDim.x) {
        int d = i / tot, rem = i % tot;
        int r = rem / C_, co = rem % C_;
        int cip = r / K_, k = r % K_;
        const float* w = ws[d];
        g_wp2[i] = pack2(w[(size_t)co * C_ * K_ + (2 * cip) * K_ + k],
                         w[(size_t)co * C_ * K_ + (2 * cip + 1) * K_ + k]);
    }
}

// Persistent pass kernel: forward scan with wpA, then backward with wpB.
// Cluster of 8 CTAs = one image; CTA 'slice' owns c_out [slice*16, slice*16+16).
// Weights staged in smem ONCE per direction. Each step: stage prev row from L2,
// compute, write-only STG of cur row, one cluster barrier.
// Thread map t = jg*16 + co (co fastest): conflict-free smem loads.
template <int L, int JT, int NT>
__global__ void __launch_bounds__(NT, 1) __cluster_dims__(NCTA, 1, 1)
pass_kernel(float* __restrict__ base, const u64* __restrict__ wpA,
            const u64* __restrict__ wpB, int nrows) {
    constexpr int QW = L + 8;                    // paired window width (4-halo)
    extern __shared__ __align__(16) u64 sm[];
    u64* w_s = sm;                               // [NR][16 co]
    u64* p_s = sm + NR * TCO;                    // [NCIP][QW]

    const int t = threadIdx.x;
    const int slice = blockIdx.x;                // 0..7 (cluster rank)
    const int b = blockIdx.y;
    const int cobase = slice * TCO;
    float* __restrict__ bb = base + (size_t)b * BS;

    const int co = t & 15;
    const int jg = t >> 4;
    const int j0 = jg * JT;
    const int gco = cobase + co;

    for (int dir = 0; dir < 2; ++dir) {
        const u64* __restrict__ wp2 = dir ? wpB : wpA;

        // ---- stage this slice's weights ONCE per direction ----
        __syncthreads();                          // prior step fully done with w_s
        {
            const uint32_t wb = (uint32_t)__cvta_generic_to_shared(w_s);
            #pragma unroll
            for (int i = t; i < NR * 8; i += NT) {
                int r = i >> 3, c = i & 7;
                cp_async16(wb + (uint32_t)i * 16u,
                           wp2 + (size_t)r * C_ + cobase + 2 * c);
            }
            cp_async_wait_all();
        }

        for (int s = 1; s < nrows; ++s) {
            const int cur = dir ? (nrows - 1 - s) : s;
            const int prev = dir ? (cur + 1) : (cur - 1);
            const float* __restrict__ prow = bb + (size_t)prev * L;
            float* __restrict__ crow = bb + (size_t)cur * L;

            // ---- stage prev row (all 128 ci) as paired u64, zero halo ----
            #pragma unroll 4
            for (int i = t; i < NCIP * QW; i += NT) {
                int cip = i / QW, q = i % QW;
                int gj = q - 4;
                float a = 0.f, c = 0.f;
                if (gj >= 0 && gj < L) {
                    a = prow[(size_t)(2 * cip) * CS + gj];
                    c = prow[(size_t)(2 * cip + 1) * CS + gj];
                }
                p_s[i] = pack2(a, c);
            }
            // ---- prefetch cur-row base values (own slice; untouched this pass) ----
            float xv[JT];
            #pragma unroll
            for (int n = 0; n < JT; ++n)
                xv[n] = crow[(size_t)gco * CS + j0 + n];

            __syncthreads();                      // p_s (and 1st-iter w_s) visible

            u64 acc[JT];
            #pragma unroll
            for (int n = 0; n < JT; ++n) acc[n] = 0ull;

            const u64* pw = p_s + j0;
            const u64* wc = w_s + co;

            #pragma unroll 1
            for (int cip = 0; cip < NCIP; ++cip) {
                u64 win[JT + 8];
                #pragma unroll
                for (int q = 0; q < JT + 8; ++q) win[q] = pw[q];
                #pragma unroll
                for (int k = 0; k < K_; ++k) {
                    const u64 wk = wc[(size_t)(cip * K_ + k) * TCO];
                    #pragma unroll
                    for (int n = 0; n < JT; ++n) fma2(acc[n], wk, win[k + n]);
                }
                pw += QW;
            }

            // ---- write-only store of cur row (own slice) ----
            #pragma unroll
            for (int n = 0; n < JT; ++n)
                crow[(size_t)gco * CS + j0 + n] =
                    xv[n] + fmaxf(hsum2(acc[n]), 0.f);

            // release our stores / acquire peers' for next step
            cluster_barrier();
        }
    }
}

// Transpose per (b,c) slab: src slab R x Cc (row-major) -> dst slab Cc x R.
__global__ void transpose_kernel(const float* __restrict__ src, float* __restrict__ dst,
                                 int R, int Cc) {
    __shared__ float tile[32][33];
    const size_t slab = blockIdx.z;
    const float* s = src + slab * (size_t)(R * Cc);
    float* d = dst + slab * (size_t)(R * Cc);
    const int c0 = blockIdx.x * 32;
    const int r0 = blockIdx.y * 32;

    #pragma unroll
    for (int i = 0; i < 32; i += 8) {
        int r = r0 + threadIdx.y + i, c = c0 + threadIdx.x;
        if (r < R && c < Cc) tile[threadIdx.y + i][threadIdx.x] = s[(size_t)r * Cc + c];
    }
    __syncthreads();
    #pragma unroll
    for (int i = 0; i < 32; i += 8) {
        int c = c0 + threadIdx.y + i, r = r0 + threadIdx.x;
        if (r < R && c < Cc) d[(size_t)c * R + r] = tile[threadIdx.x][threadIdx.y + i];
    }
}

// W pass: JT=5, NT=640 (40 jg x 16 co, 20 warps, 5/SMSP balanced)
// H pass: JT=9, NT=128 (8 jg x 16 co, 4 warps, 1/SMSP balanced)
constexpr int SMEM_W = NR * TCO * 8 + NCIP * (W_ + 8) * 8;  // 180,224 B
constexpr int SMEM_H = NR * TCO * 8 + NCIP * (H_ + 8) * 8;  // 114,688 B
static_assert(SMEM_W <= 227 * 1024, "smem W over limit");
static_assert(SMEM_H <= 227 * 1024, "smem H over limit");

extern "C" void kernel_launch(void* const* d_in, const int* in_sizes, int n_in,
                              void* d_out, int out_size) {
    const float* x  = (const float*)d_in[0];
    const float* wd = (const float*)d_in[1];
    const float* wu = (const float*)d_in[2];
    const float* wr = (const float*)d_in[3];
    const float* wl = (const float*)d_in[4];
    float* out = (float*)d_out;

    // one-time setup on the (uncaptured) correctness call only
    static float* tbuf = nullptr;
    static u64* wp = nullptr;
    static bool init_done = false;
    if (!init_done) {
        cudaGetSymbolAddress((void**)&tbuf, g_tbuf);
        cudaGetSymbolAddress((void**)&wp, g_wp2);
        cudaFuncSetAttribute((const void*)pass_kernel<W_, 5, 640>,
                             cudaFuncAttributeMaxDynamicSharedMemorySize, SMEM_W);
        cudaFuncSetAttribute((const void*)pass_kernel<H_, 9, 128>,
                             cudaFuncAttributeMaxDynamicSharedMemorySize, SMEM_H);
        init_done = true;
    }

    // re-lay-out weights (reads inputs every call -> deterministic)
    prep_weights<<<256, 256>>>(wd, wu, wr, wl);

    // working copy of x (scan runs in-place on out)
    cudaMemcpyAsync(out, x, TOTAL * sizeof(float), cudaMemcpyDeviceToDevice);

    const size_t DSTR = (size_t)NR * C_;
    const u64* wpd = wp + 0 * DSTR;
    const u64* wpu = wp + 1 * DSTR;
    const u64* wpr = wp + 2 * DSTR;
    const u64* wpl = wp + 3 * DSTR;

    // ---- down + up: conv along W (contiguous), scan over H (persistent) ----
    pass_kernel<W_, 5, 640><<<dim3(NCTA, B_), 640, SMEM_W>>>(out, wpd, wpu, H_);

    // ---- transpose (B,C,H,W) -> (B,C,W,H) ----
    const dim3 tb(32, 8);
    const dim3 tg1((W_ + 31) / 32, (H_ + 31) / 32, B_ * C_);
    transpose_kernel<<<tg1, tb>>>(out, tbuf, H_, W_);

    // ---- right + left: conv along H (now contiguous), scan over W ----
    pass_kernel<H_, 9, 128><<<dim3(NCTA, B_), 128, SMEM_H>>>(tbuf, wpr, wpl, W_);

    // ---- transpose back ----
    const dim3 tg2((H_ + 31) / 32, (W_ + 31) / 32, B_ * C_);
    transpose_kernel<<<tg2, tb>>>(tbuf, out, W_, H_);
}

// round 14
// speedup vs baseline: 1.9349x; 1.9349x over previous
#include <cuda_runtime.h>
#include <cstdint>

using u64 = unsigned long long;

// Problem constants
constexpr int B_ = 16, C_ = 128, H_ = 72, W_ = 200, K_ = 9;
constexpr int CS = H_ * W_;
constexpr int NCIP = 64;                  // ci pairs
constexpr int NR = NCIP * K_;             // 576 weight rows
constexpr int QW_W = W_ + 8;              // 208 (4-halo each side)
constexpr int QW_H = H_ + 8;              // 80
constexpr int RSTR_W = NCIP * QW_W;       // 13312 u64 per row
constexpr int RSTR_H = NCIP * QW_H;       // 5120 u64 per row

// Persistent paired-with-halo buffers + per-slice weight images
__device__ __align__(16) u64 g_pw[(size_t)B_ * H_ * RSTR_W];   // 122.7 MB
__device__ __align__(16) u64 g_ph[(size_t)B_ * W_ * RSTR_H];   // 131 MB
__device__ __align__(16) u64 g_ws[4 * 8 * NR * 16];            // [dir][slice][r][16co]

// ---------------- helpers ----------------
__device__ __forceinline__ uint32_t smem_u32(const void* p) {
    uint32_t a;
    asm("{ .reg .u64 t; cvta.to.shared.u64 t, %1; cvt.u32.u64 %0, t; }" : "=r"(a) : "l"(p));
    return a;
}
__device__ __forceinline__ void fma2(u64& d, u64 a, u64 b) {
    asm("fma.rn.f32x2 %0, %1, %2, %0;" : "+l"(d) : "l"(a), "l"(b));
}
__device__ __forceinline__ u64 add2(u64 a, u64 b) {
    u64 r; asm("add.rn.f32x2 %0, %1, %2;" : "=l"(r) : "l"(a), "l"(b)); return r;
}
__device__ __forceinline__ u64 pack2(float a, float b) {
    u64 r; asm("mov.b64 %0, {%1, %2};" : "=l"(r) : "f"(a), "f"(b)); return r;
}
__device__ __forceinline__ void unpack2(u64 v, float& x, float& y) {
    asm("mov.b64 {%0, %1}, %2;" : "=f"(x), "=f"(y) : "l"(v));
}
#define MBAR_INIT(a, n) \
    asm volatile("mbarrier.init.shared.b64 [%0], %1;" :: "r"(a), "r"(n) : "memory")
#define MBAR_EXPECT_TX(a, n) \
    asm volatile("mbarrier.arrive.expect_tx.shared.b64 _, [%0], %1;" :: "r"(a), "r"(n) : "memory")
#define MBAR_WAIT(a, ph) do { \
    asm volatile("{\n\t.reg .pred P;\n\tWL_%=:\n\t" \
        "mbarrier.try_wait.parity.acquire.cta.shared::cta.b64 P, [%0], %1, 0x989680;\n\t" \
        "@P bra.uni WD_%=;\n\tbra.uni WL_%=;\n\tWD_%=:\n\t}" \
        :: "r"(a), "r"(ph) : "memory"); } while (0)
__device__ __forceinline__ void bulk_cp(uint32_t dst, const void* src, uint32_t bytes,
                                        uint32_t mbar) {
    asm volatile(
        "cp.async.bulk.shared::cluster.global.mbarrier::complete_tx::bytes [%0], [%1], %2, [%3];"
        :: "r"(dst), "l"(src), "r"(bytes), "r"(mbar) : "memory");
}

// ---------------- weight prep: per-(dir,slice) contiguous paired slices ----------------
__global__ void prep_weights(const float* w0, const float* w1,
                             const float* w2, const float* w3) {
    const float* ws[4] = {w0, w1, w2, w3};
    const int tot = 4 * 8 * NR * 16;
    for (int i = blockIdx.x * blockDim.x + threadIdx.x; i < tot;
         i += gridDim.x * blockDim.x) {
        int c = i & 15;
        int r = (i >> 4) % NR;
        int slice = (i / (16 * NR)) & 7;
        int d = i / (16 * NR * 8);
        int co = slice * 16 + c;
        int cip = r / K_, k = r % K_;
        const float* w = ws[d];
        g_ws[i] = pack2(w[(size_t)co * (C_ * K_) + (2 * cip) * K_ + k],
                        w[(size_t)co * (C_ * K_) + (2 * cip + 1) * K_ + k]);
    }
}

// ---------------- layout conversions ----------------
// x (B,C,H,W) -> PW[b][h][cip][208] paired with zero halos
__global__ void conv_in(const float* __restrict__ x) {
    const size_t tot = (size_t)B_ * H_ * RSTR_W;
    for (size_t i = (size_t)blockIdx.x * blockDim.x + threadIdx.x; i < tot;
         i += (size_t)gridDim.x * blockDim.x) {
        int q = (int)(i % QW_W);
        size_t r = i / QW_W;
        int cip = (int)(r % NCIP);
        size_t r2 = r / NCIP;
        int h = (int)(r2 % H_);
        int b = (int)(r2 / H_);
        int j = q - 4;
        u64 v = 0;
        if (j >= 0 && j < W_) {
            size_t base = ((size_t)b * C_ + 2 * cip) * CS + (size_t)h * W_ + j;
            v = pack2(x[base], x[base + CS]);
        }
        g_pw[i] = v;
    }
}

// zero halos of PH
__global__ void zero_ph_halo() {
    const int tot = B_ * W_ * NCIP;
    for (int i = blockIdx.x * blockDim.x + threadIdx.x; i < tot;
         i += gridDim.x * blockDim.x) {
        u64* p = g_ph + (size_t)i * QW_H;
        #pragma unroll
        for (int q = 0; q < 4; ++q) { p[q] = 0; p[QW_H - 4 + q] = 0; }
    }
}

// PW -> PH: per (b,cip) transpose [h][w] -> [w][h] of u64 pairs
__global__ void conv_wh() {
    __shared__ u64 tile[32][33];
    const int slab = blockIdx.z;
    const int cip = slab & 63, b = slab >> 6;
    const int w0 = blockIdx.x * 32, h0 = blockIdx.y * 32;
    #pragma unroll
    for (int i = 0; i < 32; i += 8) {
        int h = h0 + threadIdx.y + i, w = w0 + threadIdx.x;
        if (h < H_ && w < W_)
            tile[threadIdx.y + i][threadIdx.x] =
                g_pw[(size_t)(b * H_ + h) * RSTR_W + cip * QW_W + 4 + w];
    }
    __syncthreads();
    #pragma unroll
    for (int i = 0; i < 32; i += 8) {
        int w = w0 + threadIdx.y + i, h = h0 + threadIdx.x;
        if (h < H_ && w < W_)
            g_ph[(size_t)(b * W_ + w) * RSTR_H + cip * QW_H + 4 + h] =
                tile[threadIdx.x][threadIdx.y + i];
    }
}

// PH -> out (B,C,H,W) fp32
__global__ void conv_out(float* __restrict__ out) {
    __shared__ u64 tile[32][33];
    const int slab = blockIdx.z;
    const int cip = slab & 63, b = slab >> 6;
    const int h0 = blockIdx.x * 32, w0 = blockIdx.y * 32;
    #pragma unroll
    for (int i = 0; i < 32; i += 8) {
        int w = w0 + threadIdx.y + i, h = h0 + threadIdx.x;
        if (h < H_ && w < W_)
            tile[threadIdx.y + i][threadIdx.x] =
                g_ph[(size_t)(b * W_ + w) * RSTR_H + cip * QW_H + 4 + h];
    }
    __syncthreads();
    #pragma unroll
    for (int i = 0; i < 32; i += 8) {
        int h = h0 + threadIdx.y + i, w = w0 + threadIdx.x;
        if (h < H_ && w < W_) {
            float lo, hi;
            unpack2(tile[threadIdx.x][threadIdx.y + i], lo, hi);
            size_t base = ((size_t)b * C_ + 2 * cip) * CS + (size_t)h * W_ + w;
            out[base] = lo;
            out[base + CS] = hi;
        }
    }
}

// ---------------- scan step ----------------
// cur[b,co,j] += relu( sum_{ci,k} w[co,ci,k] * prev[b,ci,j+k-4] )
// buf = paired-halo layout [row][cip][QW]. grid (8 slices, 16 b).
// Split-cip: halves of the block each cover 32 cips; partials merged via smem.
// Thread map within half: tt = jg*8 + cog (cog fastest -> conflict-free smem).
template <int L, int JT, int NT>
__global__ void __launch_bounds__(NT, 1)
step_pk(u64* __restrict__ buf, const u64* __restrict__ wbase,
        int prevIdx, int curIdx, int nrows) {
    constexpr int QW = L + 8;
    constexpr int RSTR = NCIP * QW;
    constexpr int NH = NT / 2;
    constexpr int NJG = L / JT;
    static_assert(NH == NJG * 8, "thread map mismatch");

    extern __shared__ __align__(16) u64 sm[];
    u64* w_s = sm;                         // [576][16]
    u64* p_s = sm + NR * 16;               // [64][QW]
    u64* red = p_s + NCIP * QW;            // [NH][2*JT]
    const uint32_t mbar = smem_u32(red + NH * 2 * JT);

    const int t = threadIdx.x;
    const int slice = blockIdx.x;
    const int b = blockIdx.y;
    u64* rowb = buf + (size_t)b * nrows * RSTR;

    const int half = (t >= NH);
    const int tt = half ? t - NH : t;
    const int cog = tt & 7;
    const int jg = tt >> 3;
    const int j0 = jg * JT;

    if (t == 0) MBAR_INIT(mbar, 1);
    __syncthreads();
    if (t == 0) {
        MBAR_EXPECT_TX(mbar, (uint32_t)(NR * 16 * 8 + RSTR * 8));
        bulk_cp(smem_u32(w_s), wbase + (size_t)slice * NR * 16, NR * 16 * 8, mbar);
        bulk_cp(smem_u32(p_s), rowb + (size_t)prevIdx * RSTR, RSTR * 8, mbar);
    }

    u64* crow = rowb + (size_t)curIdx * RSTR + (slice * 8 + cog) * QW + 4 + j0;
    u64 xv[JT];
    if (!half) {
        #pragma unroll
        for (int n = 0; n < JT; ++n) xv[n] = crow[n];
    }

    MBAR_WAIT(mbar, 0);

    u64 acc0[JT], acc1[JT];
    #pragma unroll
    for (int n = 0; n < JT; ++n) { acc0[n] = 0ull; acc1[n] = 0ull; }

    const u64* pw = p_s + (half ? 32 * QW : 0) + j0;
    const u64* wc = w_s + (half ? 32 * K_ * 16 : 0) + 2 * cog;

    #pragma unroll 1
    for (int cip = 0; cip < 32; ++cip) {
        u64 win[JT + 8];
        #pragma unroll
        for (int q = 0; q < JT + 8; ++q) win[q] = pw[q];
        #pragma unroll
        for (int k = 0; k < K_; ++k) {
            const ulonglong2 wp = *(const ulonglong2*)(wc + k * 16);
            #pragma unroll
            for (int n = 0; n < JT; ++n) {
                fma2(acc0[n], wp.x, win[k + n]);
                fma2(acc1[n], wp.y, win[k + n]);
            }
        }
        pw += QW;
        wc += K_ * 16;
    }

    if (half) {
        u64* rd = red + (size_t)tt * (2 * JT);
        #pragma unroll
        for (int n = 0; n < JT; ++n) { rd[n] = acc0[n]; rd[JT + n] = acc1[n]; }
    }
    __syncthreads();
    if (!half) {
        const u64* rd = red + (size_t)tt * (2 * JT);
        #pragma unroll
        for (int n = 0; n < JT; ++n) {
            u64 a0 = add2(acc0[n], rd[n]);
            u64 a1 = add2(acc1[n], rd[JT + n]);
            float x0, y0, x1, y1, vx, vy;
            unpack2(a0, x0, y0);
            unpack2(a1, x1, y1);
            unpack2(xv[n], vx, vy);
            crow[n] = pack2(vx + fmaxf(x0 + y0, 0.f), vy + fmaxf(x1 + y1, 0.f));
        }
    }
}

// W pass: JT=5, NT=640 (2 halves x 40jg x 8cog; 20 warps, 5/SMSP)
// H pass: JT=3, NT=384 (2 halves x 24jg x 8cog; 12 warps, 3/SMSP)
constexpr int SMEM_W = (NR * 16 + NCIP * QW_W + 320 * 10) * 8 + 16;  // 205,840
constexpr int SMEM_H = (NR * 16 + NCIP * QW_H + 192 * 6) * 8 + 16;   // 123,920
static_assert(SMEM_W <= 227 * 1024, "smem W over limit");
static_assert(SMEM_H <= 227 * 1024, "smem H over limit");

extern "C" void kernel_launch(void* const* d_in, const int* in_sizes, int n_in,
                              void* d_out, int out_size) {
    const float* x  = (const float*)d_in[0];
    const float* wd = (const float*)d_in[1];
    const float* wu = (const float*)d_in[2];
    const float* wr = (const float*)d_in[3];
    const float* wl = (const float*)d_in[4];
    float* out = (float*)d_out;

    // one-time setup on the (uncaptured) correctness call only
    static u64* pw = nullptr;
    static u64* ph = nullptr;
    static u64* ws = nullptr;
    static bool init_done = false;
    if (!init_done) {
        cudaGetSymbolAddress((void**)&pw, g_pw);
        cudaGetSymbolAddress((void**)&ph, g_ph);
        cudaGetSymbolAddress((void**)&ws, g_ws);
        cudaFuncSetAttribute((const void*)step_pk<W_, 5, 640>,
                             cudaFuncAttributeMaxDynamicSharedMemorySize, SMEM_W);
        cudaFuncSetAttribute((const void*)step_pk<H_, 3, 384>,
                             cudaFuncAttributeMaxDynamicSharedMemorySize, SMEM_H);
        init_done = true;
    }

    prep_weights<<<256, 256>>>(wd, wu, wr, wl);
    conv_in<<<2048, 256>>>(x);

    const size_t DSTR = (size_t)8 * NR * 16;   // per-direction weight stride
    const dim3 grid(8, 16);

    // ---- down / up: conv along W, scan over H ----
    for (int h = 1; h < H_; ++h)
        step_pk<W_, 5, 640><<<grid, 640, SMEM_W>>>(pw, ws + 0 * DSTR, h - 1, h, H_);
    for (int h = H_ - 2; h >= 0; --h)
        step_pk<W_, 5, 640><<<grid, 640, SMEM_W>>>(pw, ws + 1 * DSTR, h + 1, h, H_);

    // ---- PW -> PH (transpose) ----
    zero_ph_halo<<<512, 256>>>();
    conv_wh<<<dim3(7, 3, B_ * NCIP), dim3(32, 8)>>>();

    // ---- right / left: conv along H, scan over W ----
    for (int w = 1; w < W_; ++w)
        step_pk<H_, 3, 384><<<grid, 384, SMEM_H>>>(ph, ws + 2 * DSTR, w - 1, w, W_);
    for (int w = W_ - 2; w >= 0; --w)
        step_pk<H_, 3, 384><<<grid, 384, SMEM_H>>>(ph, ws + 3 * DSTR, w + 1, w, W_);

    // ---- PH -> out ----
    conv_out<<<dim3(3, 7, B_ * NCIP), dim3(32, 8)>>>(out);
}